// round 14
// baseline (speedup 1.0000x reference)
#include <cuda_runtime.h>

// FullNet_29008209117719: tau[N,48,9] = a[n,j] * T[ch,j]
//   T[ch,j] = exp(w_lin[j,ch]) * (j<2 ? 1 : FILT[j-2,ch])   (constant per launch)
//   a[n,0]=c[n,0]; a[n,1]=c[n,1]; a[n,2+g]=c[n,2+g]*sigmoid(MLP_g(t_p[n]))
// Store-bound: 453 MB output at ~6.15 TB/s. R11 slot-ordered write phase with
// PAIRED slots: each lane runs slots (m, m+64) in one sample loop -> two
// independent LDS.128+FMUL+STG.128 chains per iteration (2x store MLP in
// flight, half the loop overhead). All stores remain full 512B aligned
// warp bursts. STG.256 measured 18us slower — store width stays 128-bit.

#define NTH 256
#define NS  256            // samples per block (1 per thread)
#define ROW 432            // 48 channels * 9 species
#define NF4 (ROW / 4)      // 108 float4 per sample row
#define WCHUNK 3456        // f4s per warp slab = 32 samples * 108
#define NW  497            // total weight floats staged in smem

__device__ __constant__ unsigned char d_F16[7][16] = {
    {1,1,1,1,1,1,1,1,1,1,1,1,1,0,1,1},  // h2o
    {0,0,0,1,1,0,1,1,0,0,0,0,1,0,0,0},  // o3
    {0,0,1,1,1,1,1,1,0,0,0,1,1,1,1,0},  // co2
    {1,0,0,0,0,0,0,0,0,0,1,0,0,0,0,0},  // o2
    {0,0,1,0,0,0,0,1,1,0,0,0,1,0,1,0},  // n2o
    {0,0,0,0,0,0,0,0,1,0,0,0,0,0,0,1},  // ch4
    {0,0,0,0,0,0,0,1,0,0,0,0,1,0,0,0},  // co
};

// smem weight layout offsets
#define OFF_W1 0      // 7*6*2 = 84
#define OFF_B1 84     // 7*6   = 42
#define OFF_W2 126    // 7*4*6 = 168
#define OFF_B2 294    // 7*4   = 28
#define OFF_W3 322    // 7*4*4 = 112
#define OFF_B3 434    // 7*4   = 28
#define OFF_WO 462    // 7*4   = 28
#define OFF_BO 490    // 7     = 7   -> 497 total

__global__ __launch_bounds__(NTH) void fullnet_kernel(
    const float* __restrict__ t_p,   // [N,2]
    const float* __restrict__ c,     // [N,9]
    const float* __restrict__ w_lin, // [9,48]
    const float* __restrict__ W1, const float* __restrict__ b1,
    const float* __restrict__ W2, const float* __restrict__ b2,
    const float* __restrict__ W3, const float* __restrict__ b3,
    const float* __restrict__ Wo, const float* __restrict__ bo,
    float* __restrict__ out,         // [N,48,9]
    int Ntot)
{
    __shared__ float4 sT4[NF4];       // T table as 108 float4
    __shared__ float4 sa4[NS][9];     // per-sample pre-gathered scalars
    __shared__ float  sw[NW];         // all MLP weights

    const int tid  = threadIdx.x;
    const int lane = tid & 31;
    const int warp = tid >> 5;

    // ---- stage weights into smem ----
    for (int i = tid; i < NW; i += NTH) {
        float v;
        if      (i < OFF_B1) v = W1[i - OFF_W1];
        else if (i < OFF_W2) v = b1[i - OFF_B1];
        else if (i < OFF_B2) v = W2[i - OFF_W2];
        else if (i < OFF_W3) v = b2[i - OFF_B2];
        else if (i < OFF_B3) v = W3[i - OFF_W3];
        else if (i < OFF_WO) v = b3[i - OFF_B3];
        else if (i < OFF_BO) v = Wo[i - OFF_WO];
        else                 v = bo[i - OFF_BO];
        sw[i] = v;
    }

    // ---- build constant table T ----
    float* sTf = (float*)sT4;
    for (int k = tid; k < ROW; k += NTH) {
        int ch = k / 9, j = k % 9;
        float m = (j < 2) ? 1.0f : (float)d_F16[j - 2][ch / 3];
        sTf[k] = m * expf(w_lin[j * 48 + ch]);
    }

    // ---- per-sample loads ----
    const int n = blockIdx.x * NS + tid;
    float tt = 0.f, pp = 0.f;
    float a[9];
    if (n < Ntot) {
        tt = t_p[2 * n];
        pp = t_p[2 * n + 1];
        #pragma unroll
        for (int j = 0; j < 9; j++) a[j] = c[9 * n + j];
    } else {
        #pragma unroll
        for (int j = 0; j < 9; j++) a[j] = 0.f;
    }

    __syncthreads();  // sw staged

    // ---- MLPs (one sample per thread); a[2+g] *= sigmoid(ke_g) ----
    #pragma unroll 1
    for (int g = 0; g < 7; g++) {
        const float* w1 = &sw[OFF_W1 + g * 12];
        const float* B1 = &sw[OFF_B1 + g * 6];
        float h1[6];
        #pragma unroll
        for (int h = 0; h < 6; h++) {
            float v = fmaf(w1[2 * h], tt, fmaf(w1[2 * h + 1], pp, B1[h]));
            h1[h] = v > 0.f ? v : 0.f;
        }
        const float* w2 = &sw[OFF_W2 + g * 24];
        const float* B2 = &sw[OFF_B2 + g * 4];
        float h2[4];
        #pragma unroll
        for (int o = 0; o < 4; o++) {
            float v = B2[o];
            #pragma unroll
            for (int h = 0; h < 6; h++) v = fmaf(w2[o * 6 + h], h1[h], v);
            h2[o] = v > 0.f ? v : 0.f;
        }
        const float* w3 = &sw[OFF_W3 + g * 16];
        const float* B3 = &sw[OFF_B3 + g * 4];
        float h3[4];
        #pragma unroll
        for (int o = 0; o < 4; o++) {
            float v = B3[o];
            #pragma unroll
            for (int h = 0; h < 4; h++) v = fmaf(w3[o * 4 + h], h2[h], v);
            h3[o] = v > 0.f ? v : 0.f;
        }
        float v = sw[OFF_BO + g];
        #pragma unroll
        for (int h = 0; h < 4; h++) v = fmaf(sw[OFF_WO + g * 4 + h], h3[h], v);
        float ke = 1.0f / (1.0f + __expf(-v));
        a[2 + g] *= ke;
    }

    // ---- pre-gather per-sample scalars: sa4[n][p] serves f4-indices ≡ p (mod 9) ----
    #pragma unroll
    for (int p = 0; p < 9; p++) {
        float4 v;
        v.x = a[(4 * p)     % 9];
        v.y = a[(4 * p + 1) % 9];
        v.z = a[(4 * p + 2) % 9];
        v.w = a[(4 * p + 3) % 9];
        sa4[tid][p] = v;
    }

    __syncwarp();  // warp w's slab (samples [32w,32w+32)) is ready

    // ---- paired-slot warp-owned write phase ----
    // Pass 0: lane L runs slots (L, L+64); pass 1: (L+32, L+96 if L<12).
    // Both t4's and both phases (pB = (pA+1)%9 since 64 ≡ 1 mod 9) are
    // loop-invariant registers. Inner loop per sample: 2 broadcast LDS.128 +
    // 8 FMUL + 2 streaming STG.128 — two independent chains in flight.
    const long long gbase = (long long)blockIdx.x * NS;
    if (gbase + NS <= Ntot) {
        const float* paw = (const float*)&sa4[warp * 32][0];  // 36 floats/sample
        float* outw = out + (size_t)(gbase + warp * 32) * ROW;

        #pragma unroll
        for (int pass = 0; pass < 2; pass++) {
            const int mA = lane + pass * 32;
            const int mB = mA + 64;
            const bool hasB = (pass == 0) || (lane < 12);  // slot 96+L only L<12
            const float4 tA = sT4[mA];
            const float4 tB = hasB ? sT4[mB] : tA;
            const int pA = mA % 9;
            int pB = pA + 1; if (pB == 9) pB = 0;          // (mA+64) % 9
            const float* paA = paw + 4 * pA;
            const float* paB = paw + 4 * pB;
            float* poA = outw + 4 * mA;
            float* poB = outw + 4 * mB;

            #pragma unroll 4
            for (int s = 0; s < 32; s++) {
                float4 aA = *(const float4*)paA;
                float4 oA;
                oA.x = aA.x * tA.x;
                oA.y = aA.y * tA.y;
                oA.z = aA.z * tA.z;
                oA.w = aA.w * tA.w;
                __stcs((float4*)poA, oA);
                if (hasB) {
                    float4 aB = *(const float4*)paB;
                    float4 oB;
                    oB.x = aB.x * tB.x;
                    oB.y = aB.y * tB.y;
                    oB.z = aB.z * tB.z;
                    oB.w = aB.w * tB.w;
                    __stcs((float4*)poB, oB);
                }
                paA += 36; paB += 36;     // next sample's sa4 row
                poA += ROW; poB += ROW;   // next sample's output row
            }
        }
    } else {
        // tail path (bounds-checked, generic)
        const float* sTs = (const float*)sT4;
        for (int i = warp * WCHUNK + lane; i < (warp + 1) * WCHUNK; i += 32) {
            int nl = i / NF4;
            if (gbase + nl >= Ntot) break;
            int k = (i - nl * NF4) * 4;
            const float* pa = (const float*)&sa4[nl][0];
            int p = i % 9;
            float4 a4 = *(const float4*)(pa + 4 * p);
            float4 o;
            o.x = a4.x * sTs[k];
            o.y = a4.y * sTs[k + 1];
            o.z = a4.z * sTs[k + 2];
            o.w = a4.w * sTs[k + 3];
            *(float4*)(out + (size_t)gbase * ROW + (size_t)4 * i) = o;
        }
    }
}

extern "C" void kernel_launch(void* const* d_in, const int* in_sizes, int n_in,
                              void* d_out, int out_size)
{
    const float* t_p   = (const float*)d_in[0];
    const float* c     = (const float*)d_in[1];
    const float* w_lin = (const float*)d_in[2];
    const float* W1    = (const float*)d_in[3];
    const float* b1    = (const float*)d_in[4];
    const float* W2    = (const float*)d_in[5];
    const float* b2    = (const float*)d_in[6];
    const float* W3    = (const float*)d_in[7];
    const float* b3    = (const float*)d_in[8];
    const float* Wo    = (const float*)d_in[9];
    const float* bo    = (const float*)d_in[10];
    float* out = (float*)d_out;

    int Ntot = in_sizes[1] / 9;   // c is [N,9]
    int nblk = (Ntot + NS - 1) / NS;
    fullnet_kernel<<<nblk, NTH>>>(t_p, c, w_lin, W1, b1, W2, b2, W3, b3, Wo, bo,
                                  out, Ntot);
}

// round 15
// speedup vs baseline: 1.0121x; 1.0121x over previous
#include <cuda_runtime.h>

// FullNet_29008209117719 — FINAL (converged at the chip's streaming-write ceiling).
//   tau[N,48,9] = a[n,j] * T[ch,j]
//   T[ch,j] = exp(w_lin[j,ch]) * (j<2 ? 1 : FILT[j-2,ch])   (constant per launch)
//   a[n,0]=c[n,0]; a[n,1]=c[n,1]; a[n,2+g]=c[n,2+g]*sigmoid(MLP_g(t_p[n]))
// Store-bound: 453 MB output at ~6.15 TB/s effective (measured optimum,
// reproduced 73.8/73.9 us). Slot-ordered warp-owned write phase: T held in
// registers per slot, sa4 read is a same-sample 144B broadcast, inner loop =
// 1 LDS.128 + 4 FMUL + 1 streaming STG.128, unroll 8.
// Tested and rejected: STG.256 (-25%), paired-slot MLP (neutral), persistent
// warps (-12%), occupancy/wave reshapes (neutral to -5%).

#define NTH 256
#define NS  256            // samples per block (1 per thread)
#define ROW 432            // 48 channels * 9 species
#define NF4 (ROW / 4)      // 108 float4 per sample row
#define WCHUNK 3456        // f4s per warp slab = 32 samples * 108
#define NW  497            // total weight floats staged in smem

__device__ __constant__ unsigned char d_F16[7][16] = {
    {1,1,1,1,1,1,1,1,1,1,1,1,1,0,1,1},  // h2o
    {0,0,0,1,1,0,1,1,0,0,0,0,1,0,0,0},  // o3
    {0,0,1,1,1,1,1,1,0,0,0,1,1,1,1,0},  // co2
    {1,0,0,0,0,0,0,0,0,0,1,0,0,0,0,0},  // o2
    {0,0,1,0,0,0,0,1,1,0,0,0,1,0,1,0},  // n2o
    {0,0,0,0,0,0,0,0,1,0,0,0,0,0,0,1},  // ch4
    {0,0,0,0,0,0,0,1,0,0,0,0,1,0,0,0},  // co
};

// smem weight layout offsets
#define OFF_W1 0      // 7*6*2 = 84
#define OFF_B1 84     // 7*6   = 42
#define OFF_W2 126    // 7*4*6 = 168
#define OFF_B2 294    // 7*4   = 28
#define OFF_W3 322    // 7*4*4 = 112
#define OFF_B3 434    // 7*4   = 28
#define OFF_WO 462    // 7*4   = 28
#define OFF_BO 490    // 7     = 7   -> 497 total

__global__ __launch_bounds__(NTH) void fullnet_kernel(
    const float* __restrict__ t_p,   // [N,2]
    const float* __restrict__ c,     // [N,9]
    const float* __restrict__ w_lin, // [9,48]
    const float* __restrict__ W1, const float* __restrict__ b1,
    const float* __restrict__ W2, const float* __restrict__ b2,
    const float* __restrict__ W3, const float* __restrict__ b3,
    const float* __restrict__ Wo, const float* __restrict__ bo,
    float* __restrict__ out,         // [N,48,9]
    int Ntot)
{
    __shared__ float4 sT4[NF4];       // T table as 108 float4
    __shared__ float4 sa4[NS][9];     // per-sample pre-gathered scalars
    __shared__ float  sw[NW];         // all MLP weights

    const int tid  = threadIdx.x;
    const int lane = tid & 31;
    const int warp = tid >> 5;

    // ---- stage weights into smem ----
    for (int i = tid; i < NW; i += NTH) {
        float v;
        if      (i < OFF_B1) v = W1[i - OFF_W1];
        else if (i < OFF_W2) v = b1[i - OFF_B1];
        else if (i < OFF_B2) v = W2[i - OFF_W2];
        else if (i < OFF_W3) v = b2[i - OFF_B2];
        else if (i < OFF_B3) v = W3[i - OFF_W3];
        else if (i < OFF_WO) v = b3[i - OFF_B3];
        else if (i < OFF_BO) v = Wo[i - OFF_WO];
        else                 v = bo[i - OFF_BO];
        sw[i] = v;
    }

    // ---- build constant table T ----
    float* sTf = (float*)sT4;
    for (int k = tid; k < ROW; k += NTH) {
        int ch = k / 9, j = k % 9;
        float m = (j < 2) ? 1.0f : (float)d_F16[j - 2][ch / 3];
        sTf[k] = m * expf(w_lin[j * 48 + ch]);
    }

    // ---- per-sample loads ----
    const int n = blockIdx.x * NS + tid;
    float tt = 0.f, pp = 0.f;
    float a[9];
    if (n < Ntot) {
        tt = t_p[2 * n];
        pp = t_p[2 * n + 1];
        #pragma unroll
        for (int j = 0; j < 9; j++) a[j] = c[9 * n + j];
    } else {
        #pragma unroll
        for (int j = 0; j < 9; j++) a[j] = 0.f;
    }

    __syncthreads();  // sw staged

    // ---- MLPs (one sample per thread); a[2+g] *= sigmoid(ke_g) ----
    #pragma unroll 1
    for (int g = 0; g < 7; g++) {
        const float* w1 = &sw[OFF_W1 + g * 12];
        const float* B1 = &sw[OFF_B1 + g * 6];
        float h1[6];
        #pragma unroll
        for (int h = 0; h < 6; h++) {
            float v = fmaf(w1[2 * h], tt, fmaf(w1[2 * h + 1], pp, B1[h]));
            h1[h] = v > 0.f ? v : 0.f;
        }
        const float* w2 = &sw[OFF_W2 + g * 24];
        const float* B2 = &sw[OFF_B2 + g * 4];
        float h2[4];
        #pragma unroll
        for (int o = 0; o < 4; o++) {
            float v = B2[o];
            #pragma unroll
            for (int h = 0; h < 6; h++) v = fmaf(w2[o * 6 + h], h1[h], v);
            h2[o] = v > 0.f ? v : 0.f;
        }
        const float* w3 = &sw[OFF_W3 + g * 16];
        const float* B3 = &sw[OFF_B3 + g * 4];
        float h3[4];
        #pragma unroll
        for (int o = 0; o < 4; o++) {
            float v = B3[o];
            #pragma unroll
            for (int h = 0; h < 4; h++) v = fmaf(w3[o * 4 + h], h2[h], v);
            h3[o] = v > 0.f ? v : 0.f;
        }
        float v = sw[OFF_BO + g];
        #pragma unroll
        for (int h = 0; h < 4; h++) v = fmaf(sw[OFF_WO + g * 4 + h], h3[h], v);
        float ke = 1.0f / (1.0f + __expf(-v));
        a[2 + g] *= ke;
    }

    // ---- pre-gather per-sample scalars: sa4[n][p] serves f4-indices ≡ p (mod 9) ----
    #pragma unroll
    for (int p = 0; p < 9; p++) {
        float4 v;
        v.x = a[(4 * p)     % 9];
        v.y = a[(4 * p + 1) % 9];
        v.z = a[(4 * p + 2) % 9];
        v.w = a[(4 * p + 3) % 9];
        sa4[tid][p] = v;
    }

    __syncwarp();  // warp w's slab (samples [32w,32w+32)) is ready

    // ---- slot-ordered warp-owned write phase ----
    // Lane L owns f4-slots m = L, L+32, L+64, (L+96 if L<12). Per slot:
    // t4 = sT4[m] held in REGISTERS for 32 samples; phase p = m % 9 constant.
    // Inner loop over the warp's 32 samples: all lanes read the SAME sample's
    // sa4 row (9 f4s in 144B -> ~2 crossbar phases) + 4 FMUL + STG.128 (.cs).
    const long long gbase = (long long)blockIdx.x * NS;
    if (gbase + NS <= Ntot) {
        const float* paw = (const float*)&sa4[warp * 32][0];  // 36 floats/sample
        float* outw = out + (size_t)(gbase + warp * 32) * ROW;

        #pragma unroll
        for (int slot = 0; slot < 4; slot++) {
            const int m = lane + slot * 32;
            if (slot == 3 && lane >= 12) break;   // only 12 lanes in last slot
            const float4 t4 = sT4[m];
            const int p = m % 9;                  // f4-index mod 9
            const float* pa = paw + 4 * p;
            float* po = outw + 4 * m;
            #pragma unroll 8
            for (int s = 0; s < 32; s++) {
                float4 a4 = *(const float4*)pa;
                float4 o;
                o.x = a4.x * t4.x;
                o.y = a4.y * t4.y;
                o.z = a4.z * t4.z;
                o.w = a4.w * t4.w;
                __stcs((float4*)po, o);
                pa += 36;      // next sample's sa4 row
                po += ROW;     // next sample's output row
            }
        }
    } else {
        // tail path (bounds-checked, generic)
        const float* sTs = (const float*)sT4;
        for (int i = warp * WCHUNK + lane; i < (warp + 1) * WCHUNK; i += 32) {
            int nl = i / NF4;
            if (gbase + nl >= Ntot) break;
            int k = (i - nl * NF4) * 4;
            const float* pa = (const float*)&sa4[nl][0];
            int p = i % 9;
            float4 a4 = *(const float4*)(pa + 4 * p);
            float4 o;
            o.x = a4.x * sTs[k];
            o.y = a4.y * sTs[k + 1];
            o.z = a4.z * sTs[k + 2];
            o.w = a4.w * sTs[k + 3];
            *(float4*)(out + (size_t)gbase * ROW + (size_t)4 * i) = o;
        }
    }
}

extern "C" void kernel_launch(void* const* d_in, const int* in_sizes, int n_in,
                              void* d_out, int out_size)
{
    const float* t_p   = (const float*)d_in[0];
    const float* c     = (const float*)d_in[1];
    const float* w_lin = (const float*)d_in[2];
    const float* W1    = (const float*)d_in[3];
    const float* b1    = (const float*)d_in[4];
    const float* W2    = (const float*)d_in[5];
    const float* b2    = (const float*)d_in[6];
    const float* W3    = (const float*)d_in[7];
    const float* b3    = (const float*)d_in[8];
    const float* Wo    = (const float*)d_in[9];
    const float* bo    = (const float*)d_in[10];
    float* out = (float*)d_out;

    int Ntot = in_sizes[1] / 9;   // c is [N,9]
    int nblk = (Ntot + NS - 1) / NS;
    fullnet_kernel<<<nblk, NTH>>>(t_p, c, w_lin, W1, b1, W2, b2, W3, b3, Wo, bo,
                                  out, Ntot);
}